// round 12
// baseline (speedup 1.0000x reference)
#include <cuda_runtime.h>
#include <cuda_bf16.h>
#include <cstdint>

#define BB 32
#define TT 2048
#define CCH 384
#define HH 64

typedef unsigned int u32;
typedef unsigned short u16;

// ---------------- global split-bf16 buffers (static: no allocs) -------------
__device__ __align__(16) u16 g_wt_hi[3 * HH * CCH];   // [w][n][k] transposed
__device__ __align__(16) u16 g_wt_lo[3 * HH * CCH];
__device__ __align__(16) u16 g_q_hi[BB * TT * HH];    // q pre-scaled by log2e/8
__device__ __align__(16) u16 g_q_lo[BB * TT * HH];
__device__ __align__(16) u16 g_k_hi[BB * TT * HH];
__device__ __align__(16) u16 g_k_lo[BB * TT * HH];
__device__ __align__(16) u16 g_v_hi[BB * TT * HH];
__device__ __align__(16) u16 g_v_lo[BB * TT * HH];

// ---------------- helpers ---------------------------------------------------
static __device__ __forceinline__ u32 smem_u32(const void* p) {
    u32 a;
    asm("{ .reg .u64 t; cvta.to.shared.u64 t, %1; cvt.u32.u64 %0, t; }" : "=r"(a) : "l"(p));
    return a;
}
static __device__ __forceinline__ void ldsm_x4(u32 r[4], u32 a) {
    asm volatile("ldmatrix.sync.aligned.m8n8.x4.shared.b16 {%0,%1,%2,%3}, [%4];"
                 : "=r"(r[0]), "=r"(r[1]), "=r"(r[2]), "=r"(r[3]) : "r"(a));
}
static __device__ __forceinline__ void ldsm_x2(u32 r[2], u32 a) {
    asm volatile("ldmatrix.sync.aligned.m8n8.x2.shared.b16 {%0,%1}, [%2];"
                 : "=r"(r[0]), "=r"(r[1]) : "r"(a));
}
static __device__ __forceinline__ void ldsm_x2t(u32 r[2], u32 a) {
    asm volatile("ldmatrix.sync.aligned.m8n8.x2.trans.shared.b16 {%0,%1}, [%2];"
                 : "=r"(r[0]), "=r"(r[1]) : "r"(a));
}
static __device__ __forceinline__ void mma_bf16(float d[4], const u32 a[4], const u32 b[2]) {
    asm volatile("mma.sync.aligned.m16n8k16.row.col.f32.bf16.bf16.f32 "
                 "{%0,%1,%2,%3}, {%4,%5,%6,%7}, {%8,%9}, {%0,%1,%2,%3};"
                 : "+f"(d[0]), "+f"(d[1]), "+f"(d[2]), "+f"(d[3])
                 : "r"(a[0]), "r"(a[1]), "r"(a[2]), "r"(a[3]), "r"(b[0]), "r"(b[1]));
}
// split a,b into bf16 hi pair + bf16 lo pair (rn rounding)
static __device__ __forceinline__ void split2(float a, float b, u32& hi, u32& lo) {
    u32 h;
    asm("cvt.rn.bf16x2.f32 %0, %1, %2;" : "=r"(h) : "f"(b), "f"(a));
    float ha = __uint_as_float(h << 16);
    float hb = __uint_as_float(h & 0xffff0000u);
    float la = a - ha;
    float lb = b - hb;
    asm("cvt.rn.bf16x2.f32 %0, %1, %2;" : "=r"(lo) : "f"(lb), "f"(la));
    hi = h;
}
static __device__ __forceinline__ float ex2(float x) {
    float y;
    asm("ex2.approx.ftz.f32 %0, %1;" : "=f"(y) : "f"(x));
    return y;
}
static __device__ __forceinline__ void cpa16(u32 dst, const void* src) {
    asm volatile("cp.async.cg.shared.global [%0], [%1], 16;" :: "r"(dst), "l"(src));
}
#define CP_COMMIT() asm volatile("cp.async.commit_group;" ::: "memory")
#define CP_WAIT1()  asm volatile("cp.async.wait_group 1;" ::: "memory")
#define CP_WAIT0()  asm volatile("cp.async.wait_group 0;" ::: "memory")

#define QSCALE 0.18033688011112042f   // (1/8) * log2(e)

// ---------------- prepass: split + transpose weights ------------------------
__global__ __launch_bounds__(256) void split_w(const float* __restrict__ Wk,
                                               const float* __restrict__ Wq,
                                               const float* __restrict__ Wv) {
    int id = blockIdx.x * blockDim.x + threadIdx.x;   // < 3*64*384
    int w = id / (HH * CCH);
    int r = id % (HH * CCH);
    int n = r / CCH;
    int k = r % CCH;
    const float* W = (w == 0) ? Wk : (w == 1) ? Wq : Wv;
    float v = W[k * HH + n];
    float h = __bfloat162float(__float2bfloat16(v));
    __nv_bfloat16 bh = __float2bfloat16(h);
    __nv_bfloat16 bl = __float2bfloat16(v - h);
    g_wt_hi[id] = *reinterpret_cast<u16*>(&bh);
    g_wt_lo[id] = *reinterpret_cast<u16*>(&bl);
}

// ---------------- projection: q/k/v = x @ W, fused 3 weights ----------------
#define XPAD 40   // smem row stride (u16) for 32-wide k chunks

__global__ __launch_bounds__(128, 3) void proj_mma(const float* __restrict__ x) {
    __shared__ u16 xs_hi[64 * XPAD], xs_lo[64 * XPAD];
    __shared__ u16 ws_hi[3 * 64 * XPAD], ws_lo[3 * 64 * XPAD];

    const int tid  = threadIdx.x;
    const int lane = tid & 31;
    const int wp   = tid >> 5;
    const int l16  = lane & 15;
    const int m0   = blockIdx.x * 64;
    const int b    = blockIdx.y;

    const u32 xhb = smem_u32(xs_hi), xlb = smem_u32(xs_lo);
    const u32 whb = smem_u32(ws_hi), wlb = smem_u32(ws_lo);

    float acc[3][8][4];
    #pragma unroll
    for (int w = 0; w < 3; w++)
        #pragma unroll
        for (int n = 0; n < 8; n++)
            #pragma unroll
            for (int j = 0; j < 4; j++) acc[w][n][j] = 0.f;

    const float* xb = x + ((size_t)b * TT + m0) * CCH;

    for (int c0 = 0; c0 < CCH; c0 += 32) {
        __syncthreads();
        {
            int row = tid >> 1, half = (tid & 1) * 16;
            const float* s = xb + (size_t)row * CCH + c0 + half;
            u16* dh = xs_hi + row * XPAD + half;
            u16* dl = xs_lo + row * XPAD + half;
            #pragma unroll
            for (int i = 0; i < 4; i++) {
                float4 v = *reinterpret_cast<const float4*>(s + i * 4);
                u32 h0, l0, h1, l1;
                split2(v.x, v.y, h0, l0);
                split2(v.z, v.w, h1, l1);
                *reinterpret_cast<uint2*>(dh + i * 4) = make_uint2(h0, h1);
                *reinterpret_cast<uint2*>(dl + i * 4) = make_uint2(l0, l1);
            }
        }
        for (int i = tid; i < 3 * 128; i += 128) {
            int w  = i >> 7;
            int c  = i & 127;
            int rr = c >> 1, ko = (c & 1) * 16;
            size_t g = ((size_t)w * HH + rr) * CCH + c0 + ko;
            u16* dh = ws_hi + (w * 64 + rr) * XPAD + ko;
            u16* dl = ws_lo + (w * 64 + rr) * XPAD + ko;
            #pragma unroll
            for (int u = 0; u < 2; u++) {
                *reinterpret_cast<uint4*>(dh + u * 8) =
                    *reinterpret_cast<const uint4*>(g_wt_hi + g + u * 8);
                *reinterpret_cast<uint4*>(dl + u * 8) =
                    *reinterpret_cast<const uint4*>(g_wt_lo + g + u * 8);
            }
        }
        __syncthreads();

        #pragma unroll
        for (int ks = 0; ks < 2; ks++) {
            u32 ah[4], al[4];
            int arow = wp * 16 + (lane & 7) + ((lane >> 3) & 1) * 8;
            u32 aoff = arow * (XPAD * 2) + ks * 32 + (lane >> 4) * 16;
            ldsm_x4(ah, xhb + aoff);
            ldsm_x4(al, xlb + aoff);
            #pragma unroll
            for (int w = 0; w < 3; w++) {
                #pragma unroll
                for (int n = 0; n < 8; n++) {
                    u32 boff = (u32)(w * 64 + n * 8 + (l16 & 7)) * (XPAD * 2) + ks * 32 + (l16 >> 3) * 16;
                    u32 bh[2], bl[2];
                    ldsm_x2(bh, whb + boff);
                    ldsm_x2(bl, wlb + boff);
                    mma_bf16(acc[w][n], ah, bh);
                    mma_bf16(acc[w][n], ah, bl);
                    mma_bf16(acc[w][n], al, bh);
                }
            }
        }
    }

    #pragma unroll
    for (int w = 0; w < 3; w++) {
        u16 *dh, *dl;
        float scale = 1.f;
        if (w == 0)      { dh = g_k_hi; dl = g_k_lo; }
        else if (w == 1) { dh = g_q_hi; dl = g_q_lo; scale = QSCALE; }
        else             { dh = g_v_hi; dl = g_v_lo; }
        #pragma unroll
        for (int n = 0; n < 8; n++) {
            int col = n * 8 + (lane & 3) * 2;
            #pragma unroll
            for (int half = 0; half < 2; half++) {
                int row = m0 + wp * 16 + (lane >> 2) + half * 8;
                u32 hi, lo;
                split2(acc[w][n][half * 2] * scale, acc[w][n][half * 2 + 1] * scale, hi, lo);
                size_t o = ((size_t)b * TT + row) * HH + col;
                *reinterpret_cast<u32*>(dh + o) = hi;
                *reinterpret_cast<u32*>(dl + o) = lo;
            }
        }
    }
}

// ---------------- attention: 128-row Q tile, 256 thr, Q in smem -------------
// Tile row layout (64x64 u16 or 128x64 u16): 128B/row, 16B chunk c at
// byte row*128 + ((c ^ (row&7))*16). Conflict-free for all phases used.
#define ARRB  8192               // bytes per 64x64 u16 tile
#define STGB  (4 * ARRB)         // bytes per K/V stage = 32768
#define QREGB 32768              // Q hi (16KB) + Q lo (16KB)
#define ATTN_SMEM (QREGB + 2 * STGB)   // 98304

#define SWX(row, c) ((u32)(row) * 128u + (u32)(((c) ^ ((row) & 7)) * 16))

__global__ __launch_bounds__(256, 2) void attn_mma(float* __restrict__ out) {
    extern __shared__ u16 dynsm[];

    const int tid  = threadIdx.x;
    const int lane = tid & 31;
    const int wp   = tid >> 5;          // 0..7
    const int l16  = lane & 15;
    const int b    = blockIdx.y;
    const int qt   = gridDim.x - 1 - blockIdx.x;   // longest rows first
    const int q0   = qt * 128;
    const int wrow = wp * 16;           // warp's first row within tile

    const u32 sb0 = smem_u32(dynsm);    // Q hi base; Q lo at +16384
    const u32 stg_b[2] = { sb0 + QREGB, sb0 + QREGB + STGB };
    const int n_kt = 2 * qt + 2;

    // ---- front-load prefetch of K/V tile 0 into stage 1 --------------------
    {
        const size_t base = ((size_t)b * TT + 0) * HH;
        const u16* srcs[4] = { g_k_hi + base, g_k_lo + base, g_v_hi + base, g_v_lo + base };
        #pragma unroll
        for (int a = 0; a < 4; a++) {
            u32 dstb = stg_b[1] + a * ARRB;
            #pragma unroll
            for (int i = 0; i < 2; i++) {
                int c = tid + i * 256;
                int row = c >> 3, col = c & 7;
                cpa16(dstb + SWX(row, col), srcs[a] + (size_t)row * HH + col * 8);
            }
        }
        CP_COMMIT();
    }

    // ---- stage Q (128 rows, hi+lo) into its smem region --------------------
    {
        const u16* qh = g_q_hi + ((size_t)b * TT + q0) * HH;
        const u16* ql = g_q_lo + ((size_t)b * TT + q0) * HH;
        int row = tid >> 1, cbase = (tid & 1) * 4;
        #pragma unroll
        for (int i = 0; i < 4; i++) {
            int c = cbase + i;
            *reinterpret_cast<uint4*>((char*)dynsm + SWX(row, c)) =
                *reinterpret_cast<const uint4*>(qh + (size_t)row * HH + c * 8);
            *reinterpret_cast<uint4*>((char*)dynsm + 16384 + SWX(row, c)) =
                *reinterpret_cast<const uint4*>(ql + (size_t)row * HH + c * 8);
        }
    }
    __syncthreads();

    float Oacc[8][4];
    #pragma unroll
    for (int n = 0; n < 8; n++)
        #pragma unroll
        for (int j = 0; j < 4; j++) Oacc[n][j] = 0.f;

    float mrow[2] = { -1e30f, -1e30f };
    float lrow[2] = { 0.f, 0.f };
    const int qrow0 = q0 + wrow + (lane >> 2);

    for (int kt = 0; kt < n_kt; kt++) {
        const int k0 = kt * 64;
        // prefetch kt+1 into stage kt&1 (tile kt lives in stage (kt+1)&1)
        if (kt + 1 < n_kt) {
            const size_t base = ((size_t)b * TT + (kt + 1) * 64) * HH;
            const u16* srcs[4] = { g_k_hi + base, g_k_lo + base, g_v_hi + base, g_v_lo + base };
            u32 sbase = stg_b[kt & 1];
            #pragma unroll
            for (int a = 0; a < 4; a++) {
                u32 dstb = sbase + a * ARRB;
                #pragma unroll
                for (int i = 0; i < 2; i++) {
                    int c = tid + i * 256;
                    int row = c >> 3, col = c & 7;
                    cpa16(dstb + SWX(row, col), srcs[a] + (size_t)row * HH + col * 8);
                }
            }
            CP_COMMIT();
            CP_WAIT1();
        } else {
            CP_WAIT0();
        }
        __syncthreads();

        // warp-uniform skip: tile fully masked for this warp's rows?
        const bool active = (k0 <= q0 + wrow + 15);

        if (active) {
            const u32 khb = stg_b[(kt + 1) & 1];
            const u32 klb = khb + ARRB;
            const u32 vhb = khb + 2 * ARRB;
            const u32 vlb = khb + 3 * ARRB;

            // ---- Q fragments from smem (frees 32 regs vs persistent) ----
            u32 qa_h[4][4], qa_l[4][4];
            {
                int arow = wrow + (lane & 7) + ((lane >> 3) & 1) * 8;
                #pragma unroll
                for (int ks = 0; ks < 4; ks++) {
                    int c = ks * 2 + (lane >> 4);
                    ldsm_x4(qa_h[ks], sb0 + SWX(arow, c));
                    ldsm_x4(qa_l[ks], sb0 + 16384 + SWX(arow, c));
                }
            }

            // ---- S = Q K^T (3-term split; log2 units) ----
            float S[8][4];
            #pragma unroll
            for (int n = 0; n < 8; n++)
                #pragma unroll
                for (int j = 0; j < 4; j++) S[n][j] = 0.f;

            #pragma unroll
            for (int n = 0; n < 8; n++) {
                int brow = n * 8 + (l16 & 7);
                #pragma unroll
                for (int ks = 0; ks < 4; ks++) {
                    int c = ks * 2 + (l16 >> 3);
                    u32 boff = SWX(brow, c);
                    u32 bh[2], bl[2];
                    ldsm_x2(bh, khb + boff);
                    ldsm_x2(bl, klb + boff);
                    mma_bf16(S[n], qa_h[ks], bh);
                    mma_bf16(S[n], qa_h[ks], bl);
                    mma_bf16(S[n], qa_l[ks], bh);
                }
            }

            // ---- causal mask (only when diagonal crosses this warp) ----
            if (k0 + 63 > q0 + wrow) {
                #pragma unroll
                for (int n = 0; n < 8; n++) {
                    int colb = k0 + n * 8 + (lane & 3) * 2;
                    #pragma unroll
                    for (int j = 0; j < 4; j++) {
                        int col = colb + (j & 1);
                        int row = qrow0 + (j >> 1) * 8;
                        if (col > row) S[n][j] = -1e30f;
                    }
                }
            }

            // ---- online softmax (base-2, bare ex2) ----
            float fac[2];
            #pragma unroll
            for (int h = 0; h < 2; h++) {
                float mx = -1e30f;
                #pragma unroll
                for (int n = 0; n < 8; n++)
                    mx = fmaxf(mx, fmaxf(S[n][h * 2], S[n][h * 2 + 1]));
                mx = fmaxf(mx, __shfl_xor_sync(0xffffffffu, mx, 1));
                mx = fmaxf(mx, __shfl_xor_sync(0xffffffffu, mx, 2));
                float mnew = fmaxf(mrow[h], mx);
                fac[h] = ex2(mrow[h] - mnew);
                mrow[h] = mnew;
                float sum = 0.f;
                #pragma unroll
                for (int n = 0; n < 8; n++) {
                    float p0 = ex2(S[n][h * 2]     - mnew);
                    float p1 = ex2(S[n][h * 2 + 1] - mnew);
                    S[n][h * 2] = p0;
                    S[n][h * 2 + 1] = p1;
                    sum += p0 + p1;
                }
                sum += __shfl_xor_sync(0xffffffffu, sum, 1);
                sum += __shfl_xor_sync(0xffffffffu, sum, 2);
                lrow[h] = lrow[h] * fac[h] + sum;
                #pragma unroll
                for (int n = 0; n < 8; n++) {
                    Oacc[n][h * 2]     *= fac[h];
                    Oacc[n][h * 2 + 1] *= fac[h];
                }
            }

            // ---- O += P V (reg->reg pack of P; 3-term split) ----
            #pragma unroll
            for (int ks = 0; ks < 4; ks++) {
                u32 pa_h[4], pa_l[4];
                #pragma unroll
                for (int j = 0; j < 4; j++) {
                    int n = 2 * ks + (j >> 1);
                    int base = (j & 1) * 2;
                    split2(S[n][base], S[n][base + 1], pa_h[j], pa_l[j]);
                }
                int vrow = ks * 16 + l16;
                #pragma unroll
                for (int n = 0; n < 8; n++) {
                    u32 voff = SWX(vrow, n);
                    u32 bh[2], bl[2];
                    ldsm_x2t(bh, vhb + voff);
                    ldsm_x2t(bl, vlb + voff);
                    mma_bf16(Oacc[n], pa_h, bh);
                    mma_bf16(Oacc[n], pa_h, bl);
                    mma_bf16(Oacc[n], pa_l, bh);
                }
            }
        }
        __syncthreads();   // all reads of this stage done before it is re-filled
    }

    // ---- finalize ----
    float inv0 = 1.f / lrow[0];
    float inv1 = 1.f / lrow[1];
    #pragma unroll
    for (int n = 0; n < 8; n++) {
        int col = n * 8 + (lane & 3) * 2;
        int row0 = q0 + wrow + (lane >> 2);
        float2 v0 = make_float2(Oacc[n][0] * inv0, Oacc[n][1] * inv0);
        float2 v1 = make_float2(Oacc[n][2] * inv1, Oacc[n][3] * inv1);
        *reinterpret_cast<float2*>(out + ((size_t)b * TT + row0) * HH + col) = v0;
        *reinterpret_cast<float2*>(out + ((size_t)b * TT + row0 + 8) * HH + col) = v1;
    }
}

// ---------------------------------------------------------------------------
extern "C" void kernel_launch(void* const* d_in, const int* in_sizes, int n_in,
                              void* d_out, int out_size)
{
    const float* x  = (const float*)d_in[0];
    const float* Wk = (const float*)d_in[1];
    const float* Wq = (const float*)d_in[2];
    const float* Wv = (const float*)d_in[3];
    float* out = (float*)d_out;
    (void)in_sizes; (void)n_in; (void)out_size;

    split_w<<<(3 * HH * CCH) / 256, 256>>>(Wk, Wq, Wv);

    dim3 gridP(TT / 64, BB);
    proj_mma<<<gridP, 128>>>(x);

    static int attr_set = 0;
    if (!attr_set) {
        cudaFuncSetAttribute(attn_mma, cudaFuncAttributeMaxDynamicSharedMemorySize, ATTN_SMEM);
        attr_set = 1;
    }
    dim3 gridA(TT / 128, BB);
    attn_mma<<<gridA, 256, ATTN_SMEM>>>(out);
}